// round 13
// baseline (speedup 1.0000x reference)
#include <cuda_runtime.h>
#include <cuda_bf16.h>

// HypAgg: hyperbolic graph aggregation (Poincare ball, c=1), N=1024, D=64.
// Inputs identified BY SIZE (order-agnostic): x[1024,64], adj[1024,1024],
// att_W[128,1], att_b[1]. Output: [1024,64] f32.
//
// logmap(x_i,x_j) = -alpha*x_i + beta*x_j (scalars from x2i, y2, g=x_i.x_j),
// so support_t[i] = -S*x_i + sum cv_j*x_j. Final step (HGCN quirk):
// expmap(u = x, p = support_t), then proj.
//
// K1: per-row stats (x2, left, right) once per ROW (not per edge).
// K2: warp-per-row. Pairwise g computed with COALESCED per-j loads
//     (2 cache lines / j instead of a 32-line gather) + shuffle reduce;
//     per-lane scalar pass (one edge per lane) for the transcendentals.

#define NN 1024
#define DD 64
#define MIN_NORM 1e-15f
#define ART_CLIP (1.0f - 1e-7f)
#define MAXNORM (1.0f - 4e-3f)
#define MAXNZ 96   // per-row nonzero cap (nnz ~ Binom(1024,0.02): mean 20, max ~45)

__device__ float g_x2[NN];
__device__ float g_left[NN];
__device__ float g_right[NN];

// ---------------------------------------------------------------------------
// Kernel 1: per-row stats. One warp per row.
// ---------------------------------------------------------------------------
__global__ void __launch_bounds__(256) hypagg_rows(
    const float* __restrict__ x, const float* __restrict__ W,
    const float* __restrict__ b)
{
    int r = blockIdx.x * 8 + (threadIdx.x >> 5);
    int lane = threadIdx.x & 31;
    const float* xr = x + r * DD;
    float x0 = xr[lane], x1 = xr[lane + 32];
    float x2p = x0 * x0 + x1 * x1;
    float w1p = x0 * W[lane] + x1 * W[lane + 32];
    float w2p = x0 * W[64 + lane] + x1 * W[96 + lane];
#pragma unroll
    for (int off = 16; off; off >>= 1) {
        x2p += __shfl_down_sync(0xffffffffu, x2p, off);
        w1p += __shfl_down_sync(0xffffffffu, w1p, off);
        w2p += __shfl_down_sync(0xffffffffu, w2p, off);
    }
    if (lane == 0) {
        float pn  = sqrtf(x2p);
        float pnc = fmaxf(pn, MIN_NORM);
        float z   = fminf(pn, ART_CLIP);
        float at  = 0.5f * __logf((1.0f + z) / (1.0f - z));  // artanh
        float tf  = at / pnc;
        g_x2[r]    = x2p;
        g_left[r]  = tf * w1p + b[0];
        g_right[r] = tf * w2p;
    }
}

// ---------------------------------------------------------------------------
// Kernel 2: warp-per-row. 256 CTAs x 128 threads (4 warps = 4 rows).
// ---------------------------------------------------------------------------
__global__ void __launch_bounds__(128) hypagg_main(
    const float* __restrict__ x, const float* __restrict__ adj,
    float* __restrict__ out)
{
    __shared__ int   s_cidx[4][MAXNZ];
    __shared__ float s_cv[4][MAXNZ];   // adj value first, then cv
    __shared__ float s_g[4][MAXNZ];    // per-edge dot g = x_i . x_j

    int wid  = threadIdx.x >> 5;
    int lane = threadIdx.x & 31;
    int i    = blockIdx.x * 4 + wid;

    // lane owns dims lane and lane+32 of row i
    float xi0 = x[i * DD + lane];
    float xi1 = x[i * DD + 32 + lane];

    float x2i = g_x2[i];
    float li  = g_left[i];
    float fac = fmaxf(1.0f - x2i, MIN_NORM);   // = 2/lambda_{x_i} (c=1)

    // ---- prefetch whole adj row (8 float4 per lane, MLP=8) ----
    const float4* arow = reinterpret_cast<const float4*>(adj + i * NN);
    float4 av[8];
#pragma unroll
    for (int c = 0; c < 8; ++c) av[c] = arow[c * 32 + lane];

    // ---- ballot-compact nonzeros (deterministic order) ----
    int cnt = 0;
#pragma unroll
    for (int c = 0; c < 8; ++c) {
        float vals[4] = {av[c].x, av[c].y, av[c].z, av[c].w};
        int jb = (c * 32 + lane) * 4;
#pragma unroll
        for (int r = 0; r < 4; ++r) {
            bool pred = (vals[r] != 0.0f);
            unsigned m = __ballot_sync(0xffffffffu, pred);
            if (pred) {
                int pos = cnt + __popc(m & ((1u << lane) - 1u));
                s_cidx[wid][pos] = jb + r;
                s_cv[wid][pos]   = vals[r];
            }
            cnt += __popc(m);
        }
    }
    __syncwarp();

    // ---- pass 1: coalesced per-j dot g (2 lines/j, shuffle-reduced),
    //      2-way interleave to overlap the reduce trees ----
    int k = 0;
#pragma unroll 1
    for (; k + 2 <= cnt; k += 2) {
        int j0 = s_cidx[wid][k], j1 = s_cidx[wid][k + 1];
        const float* p0 = x + j0 * DD + lane;
        const float* p1 = x + j1 * DD + lane;
        float ga = xi0 * __ldg(p0) + xi1 * __ldg(p0 + 32);
        float gb = xi0 * __ldg(p1) + xi1 * __ldg(p1 + 32);
#pragma unroll
        for (int off = 16; off; off >>= 1) {
            ga += __shfl_down_sync(0xffffffffu, ga, off);
            gb += __shfl_down_sync(0xffffffffu, gb, off);
        }
        if (lane == 0) { s_g[wid][k] = ga; s_g[wid][k + 1] = gb; }
    }
    if (k < cnt) {
        int j0 = s_cidx[wid][k];
        const float* p0 = x + j0 * DD + lane;
        float ga = xi0 * __ldg(p0) + xi1 * __ldg(p0 + 32);
#pragma unroll
        for (int off = 16; off; off >>= 1)
            ga += __shfl_down_sync(0xffffffffu, ga, off);
        if (lane == 0) s_g[wid][k] = ga;
    }
    __syncwarp();

    // ---- pass 2: per-lane edge scalars (transcendentals once per edge) ----
    float wa_sum = 0.0f;
#pragma unroll 1
    for (int base = 0; base < cnt; base += 32) {
        int e = base + lane;
        if (e < cnt) {
            int   j  = s_cidx[wid][e];
            float a  = s_cv[wid][e];
            float g  = s_g[wid][e];
            float y2 = __ldg(g_x2 + j);
            float rj = __ldg(g_right + j);
            float A   = 1.0f - 2.0f * g + y2;
            float den = fmaxf(1.0f - 2.0f * g + x2i * y2, MIN_NORM);
            float inv = 1.0f / den;
            float alpha = A * inv;              // coeff on -x_i
            float beta  = (1.0f - x2i) * inv;   // coeff on  x_j
            float sn2 = fmaxf(alpha*alpha*x2i - 2.0f*alpha*beta*g
                              + beta*beta*y2, 0.0f);
            float sn  = fmaxf(sqrtf(sn2), MIN_NORM);
            float zc  = fminf(sn, ART_CLIP);
            float at  = 0.5f * __logf((1.0f + zc) / (1.0f - zc)); // artanh
            float wpre = fac * at / sn;
            float att  = a / (1.0f + __expf(-(li + rj)));  // sigmoid * adj
            float wgt  = att * wpre;
            s_cv[wid][e] = wgt * beta;          // cv for GEMV
            wa_sum += wgt * alpha;
        }
    }
    __syncwarp();

    // S = sum w*alpha (fixed-order shuffle tree; broadcast)
#pragma unroll
    for (int off = 16; off; off >>= 1)
        wa_sum += __shfl_down_sync(0xffffffffu, wa_sum, off);
    float S = __shfl_sync(0xffffffffu, wa_sum, 0);

    // ---- warp GEMV: 2-way unroll, 4 independent chains (fixed order) ----
    float a0 = 0.0f, a1 = 0.0f, b0 = 0.0f, b1 = 0.0f;
    k = 0;
#pragma unroll 1
    for (; k + 2 <= cnt; k += 2) {
        int   j0 = s_cidx[wid][k],   j1 = s_cidx[wid][k + 1];
        float c0 = s_cv[wid][k],     c1 = s_cv[wid][k + 1];
        const float* p0 = x + j0 * DD + lane;
        const float* p1 = x + j1 * DD + lane;
        a0 += c0 * __ldg(p0);       b0 += c0 * __ldg(p0 + 32);
        a1 += c1 * __ldg(p1);       b1 += c1 * __ldg(p1 + 32);
    }
    if (k < cnt) {
        int   j0 = s_cidx[wid][k];
        float c0 = s_cv[wid][k];
        const float* p0 = x + j0 * DD + lane;
        a0 += c0 * __ldg(p0);       b0 += c0 * __ldg(p0 + 32);
    }
    float acc0 = a0 + a1, acc1 = b0 + b1;

    // ---- expmap(u = x_i, p = sp) then proj ----
    float sp0 = acc0 - S * xi0;
    float sp1 = acc1 - S * xi1;
    float p1r = sp0 * sp0 + sp1 * sp1;   // |support|^2 partial
    float p2r = xi0 * sp0 + xi1 * sp1;   // support . x_i partial
#pragma unroll
    for (int off = 16; off; off >>= 1) {
        p1r += __shfl_down_sync(0xffffffffu, p1r, off);
        p2r += __shfl_down_sync(0xffffffffu, p2r, off);
    }
    float sp2 = __shfl_sync(0xffffffffu, p1r, 0);
    float spx = __shfl_sync(0xffffffffu, p2r, 0);

    float un   = fmaxf(sqrtf(x2i), MIN_NORM);     // |u| = |x_i|
    float facp = fmaxf(1.0f - sp2, MIN_NORM);     // 2/lambda_p at p=support
    float arg  = un / facp;
    float th   = tanhf(arg);
    float sc   = th / un;                         // second = sc * x_i
    float y2e  = sc * sc * x2i;                   // |second|^2
    float xye  = sc * spx;                        // p . second
    float c1e  = 1.0f + 2.0f * xye + y2e;         // coeff on p (= sp)
    float c2e  = (1.0f - sp2) * sc;               // coeff on x_i
    float dene = fmaxf(1.0f + 2.0f * xye + sp2 * y2e, MIN_NORM);
    float idn  = 1.0f / dene;
    float res0 = (c1e * sp0 + c2e * xi0) * idn;
    float res1 = (c1e * sp1 + c2e * xi1) * idn;

    float p3 = res0 * res0 + res1 * res1;
#pragma unroll
    for (int off = 16; off; off >>= 1)
        p3 += __shfl_down_sync(0xffffffffu, p3, off);
    float r2 = __shfl_sync(0xffffffffu, p3, 0);
    float n  = fmaxf(sqrtf(r2), MIN_NORM);
    float s  = (n > MAXNORM) ? (MAXNORM / n) : 1.0f;
    out[i * DD + lane]      = res0 * s;
    out[i * DD + 32 + lane] = res1 * s;
}

extern "C" void kernel_launch(void* const* d_in, const int* in_sizes, int n_in,
                              void* d_out, int out_size)
{
    // Order-agnostic input dispatch: the four inputs have unique sizes.
    const float *x = nullptr, *adj = nullptr, *W = nullptr, *b = nullptr;
    for (int k = 0; k < n_in; ++k) {
        switch (in_sizes[k]) {
            case NN * NN: adj = (const float*)d_in[k]; break;  // 1048576
            case NN * DD: x   = (const float*)d_in[k]; break;  // 65536
            case 2 * DD:  W   = (const float*)d_in[k]; break;  // 128
            case 1:       b   = (const float*)d_in[k]; break;  // 1
        }
    }
    float* out = (float*)d_out;
    (void)out_size;

    hypagg_rows<<<NN / 8, 256>>>(x, W, b);
    hypagg_main<<<NN / 4, 128>>>(x, adj, out);
}

// round 14
// speedup vs baseline: 1.1800x; 1.1800x over previous
#include <cuda_runtime.h>
#include <cuda_bf16.h>

// HypAgg: hyperbolic graph aggregation (Poincare ball, c=1), N=1024, D=64.
// Inputs identified BY SIZE (order-agnostic): x[1024,64], adj[1024,1024],
// att_W[128,1], att_b[1]. Output: [1024,64] f32.
//
// logmap(x_i,x_j) = -alpha*x_i + beta*x_j (scalars from x2i, y2, g=x_i.x_j),
// so support_t[i] = -S*x_i + sum cv_j*x_j. Final step (HGCN quirk):
// expmap(u = x, p = support_t), then proj.
//
// K1: per-row stats (x2, left, right), one warp per row.
// K2: ONE ROW PER 64-THREAD CTA, grid=1024 (one balanced wave, ~14 warps/SM).
//     Two warps split the row: each compacts + edge-scalars its half of adj;
//     GEMV is one-dim-per-thread. R10's gather-style edge dot kept (fastest
//     measured); no shuffle trees on the per-edge path.

#define NN 1024
#define DD 64
#define MIN_NORM 1e-15f
#define ART_CLIP (1.0f - 1e-7f)
#define MAXNORM (1.0f - 4e-3f)
#define SEGCAP 64   // per-warp-segment nonzero cap (512 cols @2%: mean 10, 17sigma)

__device__ float g_x2[NN];
__device__ float g_left[NN];
__device__ float g_right[NN];

// ---------------------------------------------------------------------------
// Kernel 1: per-row stats. One warp per row.
// ---------------------------------------------------------------------------
__global__ void __launch_bounds__(256) hypagg_rows(
    const float* __restrict__ x, const float* __restrict__ W,
    const float* __restrict__ b)
{
    int r = blockIdx.x * 8 + (threadIdx.x >> 5);
    int lane = threadIdx.x & 31;
    const float* xr = x + r * DD;
    float x0 = xr[lane], x1 = xr[lane + 32];
    float x2p = x0 * x0 + x1 * x1;
    float w1p = x0 * W[lane] + x1 * W[lane + 32];
    float w2p = x0 * W[64 + lane] + x1 * W[96 + lane];
#pragma unroll
    for (int off = 16; off; off >>= 1) {
        x2p += __shfl_down_sync(0xffffffffu, x2p, off);
        w1p += __shfl_down_sync(0xffffffffu, w1p, off);
        w2p += __shfl_down_sync(0xffffffffu, w2p, off);
    }
    if (lane == 0) {
        float pn  = sqrtf(x2p);
        float pnc = fmaxf(pn, MIN_NORM);
        float z   = fminf(pn, ART_CLIP);
        float at  = 0.5f * __logf((1.0f + z) / (1.0f - z));  // artanh
        float tf  = at / pnc;
        g_x2[r]    = x2p;
        g_left[r]  = tf * w1p + b[0];
        g_right[r] = tf * w2p;
    }
}

// ---------------------------------------------------------------------------
// Kernel 2: one row per 64-thread CTA. grid = 1024.
// ---------------------------------------------------------------------------
__global__ void __launch_bounds__(64) hypagg_main(
    const float* __restrict__ x, const float* __restrict__ adj,
    float* __restrict__ out)
{
    __shared__ float s_xi[DD];
    __shared__ int   s_cidx[2 * SEGCAP];
    __shared__ float s_cv[2 * SEGCAP];   // adj value first, then cv
    __shared__ int   s_scnt[2];
    __shared__ float s_wa[2];
    __shared__ float s_red[2][2];

    int i    = blockIdx.x;
    int t    = threadIdx.x;      // 0..63
    int wid  = t >> 5;           // 0..1
    int lane = t & 31;

    // stage x_i; thread owns dim d = t for the GEMV/epilogue
    float xid = x[i * DD + t];
    s_xi[t] = xid;

    float x2i = g_x2[i];
    float li  = g_left[i];
    float fac = fmaxf(1.0f - x2i, MIN_NORM);   // = 2/lambda_{x_i} (c=1)

    // ---- prefetch this thread's share of the adj row (4 float4, MLP=4) ----
    const float4* arow = reinterpret_cast<const float4*>(adj + i * NN);
    float4 av[4];
#pragma unroll
    for (int c = 0; c < 4; ++c) av[c] = arow[c * 64 + t];

    // ---- per-warp ballot compaction into own segment (fixed order) ----
    int wbase = wid * SEGCAP;
    int cnt = 0;
#pragma unroll
    for (int c = 0; c < 4; ++c) {
        float vals[4] = {av[c].x, av[c].y, av[c].z, av[c].w};
        int jb = (c * 64 + t) * 4;
#pragma unroll
        for (int r = 0; r < 4; ++r) {
            bool pred = (vals[r] != 0.0f);
            unsigned m = __ballot_sync(0xffffffffu, pred);
            if (pred) {
                int pos = wbase + cnt + __popc(m & ((1u << lane) - 1u));
                s_cidx[pos] = jb + r;
                s_cv[pos]   = vals[r];
            }
            cnt += __popc(m);
        }
    }
    if (lane == 0) s_scnt[wid] = cnt;
    __syncthreads();

    // ---- edge scalars: one edge per lane within this warp's segment ----
    float wa_sum = 0.0f;
    const float4* xi4 = reinterpret_cast<const float4*>(s_xi);
#pragma unroll 1
    for (int base = 0; base < cnt; base += 32) {
        int e = base + lane;
        if (e < cnt) {
            int   j = s_cidx[wbase + e];
            float a = s_cv[wbase + e];
            const float4* xj = reinterpret_cast<const float4*>(x + j * DD);
            float g0 = 0.0f, g1 = 0.0f;
#pragma unroll
            for (int q = 0; q < 8; ++q) {
                float4 v = xj[q],     u = xi4[q];
                float4 w = xj[q + 8], z = xi4[q + 8];
                g0 += v.x*u.x + v.y*u.y + v.z*u.z + v.w*u.w;
                g1 += w.x*z.x + w.y*z.y + w.z*z.z + w.w*z.w;
            }
            float g  = g0 + g1;
            float y2 = __ldg(g_x2 + j);
            float rj = __ldg(g_right + j);
            float A   = 1.0f - 2.0f * g + y2;
            float den = fmaxf(1.0f - 2.0f * g + x2i * y2, MIN_NORM);
            float inv = 1.0f / den;
            float alpha = A * inv;              // coeff on -x_i
            float beta  = (1.0f - x2i) * inv;   // coeff on  x_j
            float sn2 = fmaxf(alpha*alpha*x2i - 2.0f*alpha*beta*g
                              + beta*beta*y2, 0.0f);
            float sn  = fmaxf(sqrtf(sn2), MIN_NORM);
            float zc  = fminf(sn, ART_CLIP);
            float at  = 0.5f * __logf((1.0f + zc) / (1.0f - zc)); // artanh
            float wpre = fac * at / sn;
            float att  = a / (1.0f + __expf(-(li + rj)));  // sigmoid * adj
            float wgt  = att * wpre;
            s_cv[wbase + e] = wgt * beta;       // cv for GEMV
            wa_sum += wgt * alpha;
        }
    }
    // warp-reduce wa_sum (fixed order), stash per-warp partial
#pragma unroll
    for (int off = 16; off; off >>= 1)
        wa_sum += __shfl_down_sync(0xffffffffu, wa_sum, off);
    if (lane == 0) s_wa[wid] = wa_sum;
    __syncthreads();
    float S = s_wa[0] + s_wa[1];

    // ---- GEMV: thread owns dim d = t; both segments in fixed order ----
    float a0 = 0.0f, a1 = 0.0f, a2 = 0.0f, a3 = 0.0f;
#pragma unroll 1
    for (int seg = 0; seg < 2; ++seg) {
        int base = seg * SEGCAP, cs = s_scnt[seg];
        int k = 0;
#pragma unroll 1
        for (; k + 4 <= cs; k += 4) {
            a0 += s_cv[base + k]     * __ldg(x + s_cidx[base + k]     * DD + t);
            a1 += s_cv[base + k + 1] * __ldg(x + s_cidx[base + k + 1] * DD + t);
            a2 += s_cv[base + k + 2] * __ldg(x + s_cidx[base + k + 2] * DD + t);
            a3 += s_cv[base + k + 3] * __ldg(x + s_cidx[base + k + 3] * DD + t);
        }
        if (k < cs)     a0 += s_cv[base + k]     * __ldg(x + s_cidx[base + k]     * DD + t);
        if (k + 1 < cs) a1 += s_cv[base + k + 1] * __ldg(x + s_cidx[base + k + 1] * DD + t);
        if (k + 2 < cs) a2 += s_cv[base + k + 2] * __ldg(x + s_cidx[base + k + 2] * DD + t);
    }
    float acc = (a0 + a1) + (a2 + a3);

    // ---- expmap(u = x_i, p = sp) then proj ----
    float sp = acc - S * xid;            // support_t[i][d]
    float p1 = sp * sp, p2 = xid * sp;
#pragma unroll
    for (int off = 16; off; off >>= 1) {
        p1 += __shfl_down_sync(0xffffffffu, p1, off);
        p2 += __shfl_down_sync(0xffffffffu, p2, off);
    }
    if (lane == 0) { s_red[wid][0] = p1; s_red[wid][1] = p2; }
    __syncthreads();
    float sp2 = s_red[0][0] + s_red[1][0];   // |support|^2
    float spx = s_red[0][1] + s_red[1][1];   // support . x_i
    __syncthreads();   // all reads done before s_red reuse

    float un   = fmaxf(sqrtf(x2i), MIN_NORM);     // |u| = |x_i|
    float facp = fmaxf(1.0f - sp2, MIN_NORM);     // 2/lambda_p at p=support
    float arg  = un / facp;
    float th   = tanhf(arg);
    float sc   = th / un;                         // second = sc * x_i
    float y2e  = sc * sc * x2i;                   // |second|^2
    float xye  = sc * spx;                        // p . second
    float c1e  = 1.0f + 2.0f * xye + y2e;         // coeff on p (= sp)
    float c2e  = (1.0f - sp2) * sc;               // coeff on x_i
    float dene = fmaxf(1.0f + 2.0f * xye + sp2 * y2e, MIN_NORM);
    float res  = (c1e * sp + c2e * xid) / dene;

    float p3 = res * res;
#pragma unroll
    for (int off = 16; off; off >>= 1)
        p3 += __shfl_down_sync(0xffffffffu, p3, off);
    if (lane == 0) s_red[wid][0] = p3;
    __syncthreads();
    float r2 = s_red[0][0] + s_red[1][0];
    float n  = fmaxf(sqrtf(r2), MIN_NORM);
    float s  = (n > MAXNORM) ? (MAXNORM / n) : 1.0f;
    out[i * DD + t] = res * s;
}

extern "C" void kernel_launch(void* const* d_in, const int* in_sizes, int n_in,
                              void* d_out, int out_size)
{
    // Order-agnostic input dispatch: the four inputs have unique sizes.
    const float *x = nullptr, *adj = nullptr, *W = nullptr, *b = nullptr;
    for (int k = 0; k < n_in; ++k) {
        switch (in_sizes[k]) {
            case NN * NN: adj = (const float*)d_in[k]; break;  // 1048576
            case NN * DD: x   = (const float*)d_in[k]; break;  // 65536
            case 2 * DD:  W   = (const float*)d_in[k]; break;  // 128
            case 1:       b   = (const float*)d_in[k]; break;  // 1
        }
    }
    float* out = (float*)d_out;
    (void)out_size;

    hypagg_rows<<<NN / 8, 256>>>(x, W, b);
    hypagg_main<<<NN, 64>>>(x, adj, out);
}